// round 2
// baseline (speedup 1.0000x reference)
#include <cuda_runtime.h>
#include <math.h>

// ---------------- problem constants ----------------
#define Nn    20000
#define Ee    640000
#define Pp    27
#define Mm    5000
#define MAXNb 64
#define KIN   64
#define PIN   (Pp * KIN)      // 1728
#define R2c   0.01f
#define NC    512             // 8x8x8 spatial cells for FPS pruning

// output section offsets (flattened float32 tuple concat)
#define SEC_X     0
#define SEC_COL   320000
#define SEC_ROW   640000
#define SEC_POS   960000
#define SEC_BATCH 975000
#define SEC_EA    980000

// ---------------- persistent device scratch ----------------
__device__ __align__(16) float4 g_pos4[Nn];        // x,y,z, an=|p|^2
__device__ int    g_idx[Mm];
__device__ int    g_selmap[Nn];
__device__ float  g_deg[Mm];
__device__ __align__(16) float g_acc[(size_t)Mm * PIN];   // 34.6 MB
// FPS cell structures
__device__ int    g_pcell[Nn];
__device__ int    g_cellcnt[NC];
__device__ int    g_cellstart[NC + 1];
__device__ int    g_cellfill[NC];
__device__ __align__(16) float4 g_spos[Nn];        // sorted-by-cell: x,y,z, orig idx (bits)

// ---------------- prep: pack pos + squared norm ----------------
__global__ void prep_kernel(const float* __restrict__ pos) {
    int i = blockIdx.x * blockDim.x + threadIdx.x;
    if (i >= Nn) return;
    float x = pos[3 * i], y = pos[3 * i + 1], z = pos[3 * i + 2];
    float an = __fadd_rn(__fadd_rn(__fmul_rn(x, x), __fmul_rn(y, y)), __fmul_rn(z, z));
    g_pos4[i] = make_float4(x, y, z, an);
}

// ---------------- cell sort setup ----------------
__global__ void zero_cnt_kernel() {
    if (threadIdx.x < NC) g_cellcnt[threadIdx.x] = 0;
}
__global__ void cell_hist_kernel(const float* __restrict__ pos) {
    int i = blockIdx.x * blockDim.x + threadIdx.x;
    if (i >= Nn) return;
    int cx = min((int)(pos[3 * i]     * 8.0f), 7);
    int cy = min((int)(pos[3 * i + 1] * 8.0f), 7);
    int cz = min((int)(pos[3 * i + 2] * 8.0f), 7);
    int cid = (cx << 6) | (cy << 3) | cz;
    g_pcell[i] = cid;
    atomicAdd(&g_cellcnt[cid], 1);
}
__global__ void cell_scan_kernel() {
    __shared__ int sh[NC];
    int tid = threadIdx.x;
    int v = g_cellcnt[tid];
    sh[tid] = v;
    __syncthreads();
    for (int o = 1; o < NC; o <<= 1) {
        int t = (tid >= o) ? sh[tid - o] : 0;
        __syncthreads();
        sh[tid] += t;
        __syncthreads();
    }
    g_cellstart[tid + 1] = sh[tid];
    g_cellfill[tid] = sh[tid] - v;
    if (tid == 0) g_cellstart[0] = 0;
}
__global__ void cell_scatter_kernel(const float* __restrict__ pos) {
    int i = blockIdx.x * blockDim.x + threadIdx.x;
    if (i >= Nn) return;
    int cid = g_pcell[i];
    int off = atomicAdd(&g_cellfill[cid], 1);
    g_spos[off] = make_float4(pos[3 * i], pos[3 * i + 1], pos[3 * i + 2],
                              __int_as_float(i));
}

// ---------------- FPS: single CTA, exact cell pruning ----------------
#define OFF_WINPOS 0u
#define OFF_CKEY   8192u
#define OFF_PART   12288u
#define OFF_MIND   12544u
#define OFF_CUB    92544u
#define OFF_CST    94592u
#define OFF_ACT    96644u
#define OFF_NACT   98692u
#define OFF_GKEY   98696u
#define OFF_GQ     98704u
#define FPS_SMEM   98720u

__global__ void __launch_bounds__(1024, 1) fps_kernel(const float4* __restrict__ sp) {
    extern __shared__ unsigned char s_raw[];
    float4*             s_winpos = (float4*)(s_raw + OFF_WINPOS);
    unsigned long long* s_ckey   = (unsigned long long*)(s_raw + OFF_CKEY);
    unsigned long long* s_part   = (unsigned long long*)(s_raw + OFF_PART);
    float*              s_mind   = (float*)(s_raw + OFF_MIND);
    float*              s_cub    = (float*)(s_raw + OFF_CUB);
    int*                s_cst    = (int*)(s_raw + OFF_CST);
    int*                s_act    = (int*)(s_raw + OFF_ACT);
    int*                s_nact   = (int*)(s_raw + OFF_NACT);
    unsigned long long* s_gkey   = (unsigned long long*)(s_raw + OFF_GKEY);
    float4*             s_gq     = (float4*)(s_raw + OFF_GQ);

    const int tid = threadIdx.x, lane = tid & 31, wid = tid >> 5;
    const float INF = __int_as_float(0x7f800000);

    for (int i = tid; i < Nn; i += 1024) s_mind[i] = INF;
    for (int i = tid; i < NC + 1; i += 1024) s_cst[i] = g_cellstart[i];
    __syncthreads();
    if (tid < NC) {
        s_cub[tid]  = (s_cst[tid + 1] > s_cst[tid]) ? INF : -1.0f;
        s_ckey[tid] = 0ull;
    }
    if (tid == 0) { *s_nact = 0; g_idx[0] = 0; }
    float4 q0 = g_pos4[0];
    float qx = q0.x, qy = q0.y, qz = q0.z;
    __syncthreads();

    for (int t = 0; t < Mm - 1; ++t) {
        // ---- phase 1: which cells can change? (provably-safe skip) ----
        if (tid < NC) {
            int cx = tid >> 6, cy = (tid >> 3) & 7, cz = tid & 7;
            float lx = cx * 0.125f, ly = cy * 0.125f, lz = cz * 0.125f;
            float dx = fmaxf(fmaxf(lx - qx, qx - (lx + 0.125f)), 0.0f);
            float dy = fmaxf(fmaxf(ly - qy, qy - (ly + 0.125f)), 0.0f);
            float dz = fmaxf(fmaxf(lz - qz, qz - (lz + 0.125f)), 0.0f);
            float lb2 = dx * dx + dy * dy + dz * dz;
            if (lb2 * 0.99999f < s_cub[tid]) {     // margin covers fp rounding
                int a = atomicAdd(s_nact, 1);
                s_act[a] = tid;
            }
        }
        __syncthreads();                           // S0
        // ---- phase 2: update active cells (warp per cell) ----
        int nact = *s_nact;
        for (int a = wid; a < nact; a += 32) {
            int cid = s_act[a];
            int st = s_cst[cid], en = s_cst[cid + 1];
            float bv = 0.0f; int bidx = 0x7FFFFFFF;
            float bx = 0.f, by = 0.f, bz = 0.f;
            for (int i = st + lane; i < en; i += 32) {
                float4 p = __ldg(&sp[i]);
                float dx = p.x - qx, dy = p.y - qy, dz = p.z - qz;
                float d2 = __fadd_rn(__fadd_rn(__fmul_rn(dx, dx), __fmul_rn(dy, dy)),
                                     __fmul_rn(dz, dz));
                float nm = fminf(s_mind[i], d2);
                s_mind[i] = nm;
                int oi = __float_as_int(p.w);
                if (nm > bv || (nm == bv && oi < bidx)) {
                    bv = nm; bidx = oi; bx = p.x; by = p.y; bz = p.z;
                }
            }
            unsigned vb = __float_as_uint(bv);     // bv >= 0 -> u32 order == float order
            unsigned mv = __reduce_max_sync(0xffffffffu, vb);
            unsigned ci = (vb == mv) ? (unsigned)bidx : 0xFFFFFFFFu;
            unsigned mi = __reduce_min_sync(0xffffffffu, ci);
            if (vb == mv && (unsigned)bidx == mi) {   // exactly one lane (idx unique)
                s_ckey[cid]   = ((unsigned long long)mv << 32) |
                                (unsigned long long)(0xFFFFFFFFu - mi);
                s_cub[cid]    = __uint_as_float(mv);
                s_winpos[cid] = make_float4(bx, by, bz, 0.f);
            }
        }
        __syncthreads();                           // S1
        if (tid == 1023) *s_nact = 0;
        // ---- phase 3: argmax over 512 cached cell keys ----
        unsigned long long k = (tid < NC) ? s_ckey[tid] : 0ull;
        #pragma unroll
        for (int o = 16; o; o >>= 1) {
            unsigned long long ok = __shfl_xor_sync(0xffffffffu, k, o);
            if (ok > k) k = ok;
        }
        if (lane == 0) s_part[wid] = k;
        __syncthreads();                           // S2
        if (tid < 32) {
            unsigned long long k2 = s_part[tid];
            #pragma unroll
            for (int o = 16; o; o >>= 1) {
                unsigned long long ok = __shfl_xor_sync(0xffffffffu, k2, o);
                if (ok > k2) k2 = ok;
            }
            if (tid == 0) *s_gkey = k2;
        }
        __syncthreads();                           // S3
        unsigned long long gk = *s_gkey;
        if (tid < NC && s_ckey[tid] == gk) {       // unique: key embeds unique idx
            *s_gq = s_winpos[tid];
            g_idx[t + 1] = (int)(0xFFFFFFFFu - (unsigned)(gk & 0xFFFFFFFFull));
        }
        __syncthreads();                           // S4
        float4 qn = *s_gq;
        qx = qn.x; qy = qn.y; qz = qn.z;
    }
}

// ---------------- selection map + scratch zeroing ----------------
__global__ void sel_init_kernel() {
    int i = blockIdx.x * blockDim.x + threadIdx.x;
    if (i < Nn) g_selmap[i] = -1;
}
__global__ void sel_set_kernel() {
    int m = blockIdx.x * blockDim.x + threadIdx.x;
    if (m < Mm) { g_selmap[g_idx[m]] = m; g_deg[m] = 0.0f; }
}
__global__ void zero_acc_kernel() {
    size_t i = (size_t)(blockIdx.x) * blockDim.x + threadIdx.x;
    float4* a4 = reinterpret_cast<float4*>(g_acc);
    size_t n4 = ((size_t)Mm * PIN) / 4;
    if (i < n4) a4[i] = make_float4(0.f, 0.f, 0.f, 0.f);
}

// ---------------- spline scatter: warp per edge, filtered by dst ----------------
__global__ void scatter_kernel(const float* __restrict__ x,
                               const int*   __restrict__ ei,
                               const float* __restrict__ ea) {
    int e    = (blockIdx.x * blockDim.x + threadIdx.x) >> 5;
    int lane = threadIdx.x & 31;
    if (e >= Ee) return;
    int dst = ei[Ee + e];
    int c   = g_selmap[dst];
    if (c < 0) return;
    int src = ei[e];

    float v0 = __fmul_rn(ea[3 * e + 0], 2.0f);
    float v1 = __fmul_rn(ea[3 * e + 1], 2.0f);
    float v2 = __fmul_rn(ea[3 * e + 2], 2.0f);
    float k0 = fminf(fmaxf(floorf(v0), 0.f), 1.f);
    float k1 = fminf(fmaxf(floorf(v1), 0.f), 1.f);
    float k2 = fminf(fmaxf(floorf(v2), 0.f), 1.f);
    float f0 = v0 - k0, f1 = v1 - k1, f2 = v2 - k2;
    int kb0 = (int)k0, kb1 = (int)k1, kb2 = (int)k2;

    float xj0 = x[src * KIN + lane];
    float xj1 = x[src * KIN + 32 + lane];
    float* accb = g_acc + (size_t)c * PIN;

    #pragma unroll
    for (int s = 0; s < 8; ++s) {
        int b0 = s & 1, b1 = (s >> 1) & 1, b2 = (s >> 2) & 1;
        float b = b0 ? f0 : (1.0f - f0);
        b = __fmul_rn(b, b1 ? f1 : (1.0f - f1));
        b = __fmul_rn(b, b2 ? f2 : (1.0f - f2));
        int pidx = (kb0 + b0) * 9 + (kb1 + b1) * 3 + (kb2 + b2);
        atomicAdd(&accb[pidx * KIN + lane],      __fmul_rn(b, xj0));
        atomicAdd(&accb[pidx * KIN + 32 + lane], __fmul_rn(b, xj1));
    }
    if (lane == 0) atomicAdd(&g_deg[c], 1.0f);
}

// ---------------- GEMM + root + bias + ELU (8 nodes per block, W reused) ----------------
__global__ void node_out_kernel(const float* __restrict__ x,
                                const float* __restrict__ W,
                                const float* __restrict__ rootw,
                                const float* __restrict__ bias,
                                float* __restrict__ out) {
    int m0 = blockIdx.x * 8;       // 625 blocks
    int o  = threadIdx.x;          // 0..63
    const float* a = g_acc + (size_t)m0 * PIN;
    float s[8] = {0.f, 0.f, 0.f, 0.f, 0.f, 0.f, 0.f, 0.f};
    #pragma unroll 4
    for (int k = 0; k < PIN; ++k) {
        float w = __ldg(&W[k * KIN + o]);
        #pragma unroll
        for (int j = 0; j < 8; ++j)
            s[j] += __ldg(&a[(size_t)j * PIN + k]) * w;
    }
    float b = bias[o];
    for (int j = 0; j < 8; ++j) {
        int m = m0 + j;
        float v = s[j] / fmaxf(g_deg[m], 1.0f);
        int node = g_idx[m];
        const float* xr = x + (size_t)node * KIN;
        #pragma unroll 8
        for (int i = 0; i < KIN; ++i)
            v += __ldg(&xr[i]) * __ldg(&rootw[i * KIN + o]);
        v += b;
        v = (v > 0.f) ? v : expm1f(v);
        out[SEC_X + m * KIN + o] = v;
    }
}

// ---------------- radius neighbors: block per query, ordered first-64 ----------------
__global__ void radius_kernel(float* __restrict__ out) {
    __shared__ int s_list[MAXNb];
    __shared__ int s_cnt;
    __shared__ int s_wcnt[4];
    int m = blockIdx.x, tid = threadIdx.x;
    int wid = tid >> 5, lane = tid & 31;
    int node = g_idx[m];
    float4 q = g_pos4[node];        // q.w = qn
    if (tid == 0) s_cnt = 0;
    __syncthreads();

    for (int base = 0; base < Nn; base += 128) {
        int i = base + tid;
        bool val = false;
        if (i < Nn) {
            float4 p = g_pos4[i];
            float dot = __fadd_rn(__fadd_rn(__fmul_rn(q.x, p.x), __fmul_rn(q.y, p.y)),
                                  __fmul_rn(q.z, p.z));
            float d2 = __fadd_rn(__fadd_rn(q.w, p.w), -__fmul_rn(2.0f, dot));
            val = (d2 < R2c);
        }
        unsigned bal = __ballot_sync(0xffffffffu, val);
        if (lane == 0) s_wcnt[wid] = __popc(bal);
        __syncthreads();
        int off = s_cnt;
        for (int w2 = 0; w2 < wid; ++w2) off += s_wcnt[w2];
        off += __popc(bal & ((1u << lane) - 1u));
        if (val && off < MAXNb) s_list[off] = i;
        __syncthreads();
        if (tid == 0) s_cnt += s_wcnt[0] + s_wcnt[1] + s_wcnt[2] + s_wcnt[3];
        __syncthreads();
        if (s_cnt >= MAXNb) break;
    }
    int cnt = min(s_cnt, MAXNb);
    for (int j = tid; j < MAXNb; j += 128) {
        int col = (j < cnt) ? s_list[j] : -1;
        out[SEC_COL + m * MAXNb + j] = (float)col;
        out[SEC_ROW + m * MAXNb + j] = (j < cnt) ? (float)m : -1.0f;
    }
}

// ---------------- tail gathers: pos[idx], batch[idx], edge_attr[idx] ----------------
__global__ void tail_kernel(const float* __restrict__ pos,
                            const float* __restrict__ ea,
                            float* __restrict__ out) {
    int m = blockIdx.x * blockDim.x + threadIdx.x;
    if (m >= Mm) return;
    int node = g_idx[m];
    out[SEC_POS + 3 * m + 0] = pos[3 * node + 0];
    out[SEC_POS + 3 * m + 1] = pos[3 * node + 1];
    out[SEC_POS + 3 * m + 2] = pos[3 * node + 2];
    out[SEC_BATCH + m]       = 0.0f;
    out[SEC_EA + 3 * m + 0]  = ea[3 * node + 0];
    out[SEC_EA + 3 * m + 1]  = ea[3 * node + 1];
    out[SEC_EA + 3 * m + 2]  = ea[3 * node + 2];
}

// ---------------- launch ----------------
extern "C" void kernel_launch(void* const* d_in, const int* in_sizes, int n_in,
                              void* d_out, int out_size) {
    const float* x     = (const float*)d_in[0];
    const int*   ei    = (const int*)d_in[1];
    const float* ea    = (const float*)d_in[2];
    const float* pos   = (const float*)d_in[3];
    // d_in[4] = batch (all zeros, unused)
    const float* W     = (const float*)d_in[5];
    const float* rootw = (const float*)d_in[6];
    const float* bias  = (const float*)d_in[7];
    float* out = (float*)d_out;

    cudaFuncSetAttribute(fps_kernel, cudaFuncAttributeMaxDynamicSharedMemorySize,
                         FPS_SMEM);

    prep_kernel<<<(Nn + 255) / 256, 256>>>(pos);
    zero_cnt_kernel<<<1, NC>>>();
    cell_hist_kernel<<<(Nn + 255) / 256, 256>>>(pos);
    cell_scan_kernel<<<1, NC>>>();
    cell_scatter_kernel<<<(Nn + 255) / 256, 256>>>(pos);

    float4* spos = nullptr;
    cudaGetSymbolAddress((void**)&spos, g_spos);
    fps_kernel<<<1, 1024, FPS_SMEM>>>(spos);

    sel_init_kernel<<<(Nn + 255) / 256, 256>>>();
    sel_set_kernel<<<(Mm + 255) / 256, 256>>>();
    {
        size_t n4 = ((size_t)Mm * PIN) / 4;
        zero_acc_kernel<<<(unsigned)((n4 + 255) / 256), 256>>>();
    }
    scatter_kernel<<<(Ee * 32 + 255) / 256, 256>>>(x, ei, ea);
    node_out_kernel<<<Mm / 8, KIN>>>(x, W, rootw, bias, out);
    radius_kernel<<<Mm, 128>>>(out);
    tail_kernel<<<(Mm + 127) / 128, 128>>>(pos, ea, out);
}

// round 3
// speedup vs baseline: 1.0776x; 1.0776x over previous
#include <cuda_runtime.h>
#include <math.h>

// ---------------- problem constants ----------------
#define Nn    20000
#define Ee    640000
#define Pp    27
#define Mm    5000
#define MAXNb 64
#define KIN   64
#define PIN   (Pp * KIN)      // 1728
#define R2c   0.01f
#define NC    512             // 8x8x8 spatial cells

// output section offsets (flattened float32 tuple concat)
#define SEC_X     0
#define SEC_COL   320000
#define SEC_ROW   640000
#define SEC_POS   960000
#define SEC_BATCH 975000
#define SEC_EA    980000

// ---------------- persistent device scratch ----------------
__device__ __align__(16) float4 g_pos4[Nn];   // x,y,z, |p|^2
__device__ int    g_idx[Mm];
__device__ int    g_selmap[Nn];
__device__ __align__(16) float g_acc[(size_t)Mm * PIN];   // 34.6 MB
// cell structures
__device__ int    g_pcell[Nn];
__device__ int    g_cellcnt[NC];
__device__ int    g_cellstart[NC + 1];
__device__ int    g_cellfill[NC];
__device__ __align__(16) float4 g_spos[Nn];   // cell-sorted: x,y,z, orig idx bits
// CSR edge structures
__device__ int    g_ecnt[Mm];
__device__ int    g_eoff[Mm];
__device__ int    g_efill[Mm];
__device__ int    g_elist[Ee];

// ---------------- prep: pack pos + squared norm ----------------
__global__ void prep_kernel(const float* __restrict__ pos) {
    int i = blockIdx.x * blockDim.x + threadIdx.x;
    if (i >= Nn) return;
    float x = pos[3 * i], y = pos[3 * i + 1], z = pos[3 * i + 2];
    float an = __fadd_rn(__fadd_rn(__fmul_rn(x, x), __fmul_rn(y, y)), __fmul_rn(z, z));
    g_pos4[i] = make_float4(x, y, z, an);
}

// ---------------- cell sort setup ----------------
__global__ void zero_cnt_kernel() {
    if (threadIdx.x < NC) g_cellcnt[threadIdx.x] = 0;
}
__global__ void cell_hist_kernel(const float* __restrict__ pos) {
    int i = blockIdx.x * blockDim.x + threadIdx.x;
    if (i >= Nn) return;
    int cx = min((int)(pos[3 * i]     * 8.0f), 7);
    int cy = min((int)(pos[3 * i + 1] * 8.0f), 7);
    int cz = min((int)(pos[3 * i + 2] * 8.0f), 7);
    int cid = (cx << 6) | (cy << 3) | cz;
    g_pcell[i] = cid;
    atomicAdd(&g_cellcnt[cid], 1);
}
__global__ void cell_scan_kernel() {
    __shared__ int sh[NC];
    int tid = threadIdx.x;
    int v = g_cellcnt[tid];
    sh[tid] = v;
    __syncthreads();
    for (int o = 1; o < NC; o <<= 1) {
        int t = (tid >= o) ? sh[tid - o] : 0;
        __syncthreads();
        sh[tid] += t;
        __syncthreads();
    }
    g_cellstart[tid + 1] = sh[tid];
    g_cellfill[tid] = sh[tid] - v;
    if (tid == 0) g_cellstart[0] = 0;
}
__global__ void cell_scatter_kernel(const float* __restrict__ pos) {
    int i = blockIdx.x * blockDim.x + threadIdx.x;
    if (i >= Nn) return;
    int cid = g_pcell[i];
    int off = atomicAdd(&g_cellfill[cid], 1);
    g_spos[off] = make_float4(pos[3 * i], pos[3 * i + 1], pos[3 * i + 2],
                              __int_as_float(i));
}

// ---------------- FPS: 256 threads, exact cell pruning, cheap reduce ----------------
#define OFF_MIND   0u
#define OFF_CKEY   80000u
#define OFF_WINPOS 84096u
#define OFF_CST    92288u
#define OFF_ACT    94340u
#define OFF_NACT   96388u
#define OFF_GQ     96400u
#define FPS_SMEM   96416u

__global__ void __launch_bounds__(256, 1) fps_kernel() {
    extern __shared__ unsigned char s_raw[];
    float*              s_mind   = (float*)(s_raw + OFF_MIND);
    unsigned long long* s_ckey   = (unsigned long long*)(s_raw + OFF_CKEY);
    float4*             s_winpos = (float4*)(s_raw + OFF_WINPOS);
    int*                s_cst    = (int*)(s_raw + OFF_CST);
    int*                s_act    = (int*)(s_raw + OFF_ACT);
    int*                s_nact   = (int*)(s_raw + OFF_NACT);
    float4*             s_gq     = (float4*)(s_raw + OFF_GQ);

    const int tid = threadIdx.x, lane = tid & 31, wid = tid >> 5;
    const float INF = __int_as_float(0x7f800000);
    const float4* __restrict__ sp = g_spos;

    for (int i = tid; i < Nn; i += 256) s_mind[i] = INF;
    for (int i = tid; i <= NC; i += 256) s_cst[i] = g_cellstart[i];
    __syncthreads();
    for (int c = tid; c < NC; c += 256)
        s_ckey[c] = (s_cst[c + 1] > s_cst[c])
                    ? ((unsigned long long)0x7f800000u << 32) : 0ull;
    if (tid == 0) { *s_nact = 0; g_idx[0] = 0; }
    float4 q0 = g_pos4[0];
    float qx = q0.x, qy = q0.y, qz = q0.z;
    __syncthreads();

    for (int t = 0; t < Mm - 1; ++t) {
        // ---- phase 1: activity (provably-safe cell skip) + compaction ----
        #pragma unroll
        for (int c = tid; c < NC; c += 256) {
            float cub = __uint_as_float((unsigned)(s_ckey[c] >> 32));
            int cx = c >> 6, cy = (c >> 3) & 7, cz = c & 7;
            float lx = cx * 0.125f, ly = cy * 0.125f, lz = cz * 0.125f;
            float dx = fmaxf(fmaxf(lx - qx, qx - (lx + 0.125f)), 0.0f);
            float dy = fmaxf(fmaxf(ly - qy, qy - (ly + 0.125f)), 0.0f);
            float dz = fmaxf(fmaxf(lz - qz, qz - (lz + 0.125f)), 0.0f);
            float lb2 = dx * dx + dy * dy + dz * dz;
            bool act = (lb2 * 0.99999f < cub);
            unsigned bal = __ballot_sync(0xffffffffu, act);
            int base = 0;
            if (lane == 0 && bal) base = atomicAdd(s_nact, __popc(bal));
            base = __shfl_sync(0xffffffffu, base, 0);
            if (act) s_act[base + __popc(bal & ((1u << lane) - 1u))] = c;
        }
        __syncthreads();                               // S0
        // ---- phase 2: update active cells (warp per cell) ----
        int nact = *s_nact;
        for (int a = wid; a < nact; a += 8) {
            int cid = s_act[a];
            int st = s_cst[cid], en = s_cst[cid + 1];
            float bv = 0.0f; int bidx = 0x7FFFFFFF;
            float bx = 0.f, by = 0.f, bz = 0.f;
            for (int i = st + lane; i < en; i += 32) {
                float4 p = __ldg(&sp[i]);
                float dx = p.x - qx, dy = p.y - qy, dz = p.z - qz;
                float d2 = __fadd_rn(__fadd_rn(__fmul_rn(dx, dx), __fmul_rn(dy, dy)),
                                     __fmul_rn(dz, dz));
                float nm = fminf(s_mind[i], d2);
                s_mind[i] = nm;
                int oi = __float_as_int(p.w);
                if (nm > bv || (nm == bv && oi < bidx)) {
                    bv = nm; bidx = oi; bx = p.x; by = p.y; bz = p.z;
                }
            }
            unsigned vb = __float_as_uint(bv);
            unsigned mv = __reduce_max_sync(0xffffffffu, vb);
            unsigned ci = (vb == mv) ? (unsigned)bidx : 0xFFFFFFFFu;
            unsigned mi = __reduce_min_sync(0xffffffffu, ci);
            if (vb == mv && (unsigned)bidx == mi) {    // unique winner lane
                s_ckey[cid]   = ((unsigned long long)mv << 32) |
                                (unsigned long long)(0xFFFFFFFFu - mi);
                s_winpos[cid] = make_float4(bx, by, bz, 0.f);
            }
        }
        __syncthreads();                               // S1
        if (tid == 64) *s_nact = 0;
        // ---- phase 3: warp-0-only argmax over 512 cached keys ----
        if (wid == 0) {
            unsigned long long best = 0ull; int bc = 0;
            #pragma unroll
            for (int j = 0; j < 16; ++j) {
                unsigned long long k = s_ckey[lane + 32 * j];
                if (k > best) { best = k; bc = lane + 32 * j; }
            }
            unsigned hi = (unsigned)(best >> 32), lo = (unsigned)best;
            unsigned mhi = __reduce_max_sync(0xffffffffu, hi);
            unsigned lo2 = (hi == mhi) ? lo : 0u;
            unsigned mlo = __reduce_max_sync(0xffffffffu, lo2);
            if (hi == mhi && lo == mlo) {              // unique (lo embeds idx)
                *s_gq = s_winpos[bc];
                g_idx[t + 1] = (int)(0xFFFFFFFFu - mlo);
            }
        }
        __syncthreads();                               // S2
        float4 qn = *s_gq;
        qx = qn.x; qy = qn.y; qz = qn.z;
    }
}

// ---------------- selection map ----------------
__global__ void sel_init_kernel() {
    int i = blockIdx.x * blockDim.x + threadIdx.x;
    if (i < Nn) g_selmap[i] = -1;
    if (i < Mm) g_ecnt[i] = 0;
}
__global__ void sel_set_kernel() {
    int m = blockIdx.x * blockDim.x + threadIdx.x;
    if (m < Mm) g_selmap[g_idx[m]] = m;
}

// ---------------- CSR build over selected-dst edges ----------------
__global__ void edge_hist_kernel(const int* __restrict__ ei) {
    int e = blockIdx.x * blockDim.x + threadIdx.x;
    if (e >= Ee) return;
    int c = g_selmap[ei[Ee + e]];
    if (c >= 0) atomicAdd(&g_ecnt[c], 1);
}
__global__ void edge_scan_kernel() {
    __shared__ int sh[1024];
    int tid = threadIdx.x;
    int c[5]; int s = 0;
    #pragma unroll
    for (int j = 0; j < 5; ++j) {
        int m = tid * 5 + j;
        c[j] = (m < Mm) ? g_ecnt[m] : 0;
        s += c[j];
    }
    sh[tid] = s;
    __syncthreads();
    for (int o = 1; o < 1024; o <<= 1) {
        int v = (tid >= o) ? sh[tid - o] : 0;
        __syncthreads();
        sh[tid] += v;
        __syncthreads();
    }
    int ex = (tid > 0) ? sh[tid - 1] : 0;
    #pragma unroll
    for (int j = 0; j < 5; ++j) {
        int m = tid * 5 + j;
        if (m < Mm) { g_eoff[m] = ex; g_efill[m] = ex; ex += c[j]; }
    }
}
__global__ void edge_fill_kernel(const int* __restrict__ ei) {
    int e = blockIdx.x * blockDim.x + threadIdx.x;
    if (e >= Ee) return;
    int c = g_selmap[ei[Ee + e]];
    if (c >= 0) {
        int p = atomicAdd(&g_efill[c], 1);
        g_elist[p] = e;
    }
}

// ---------------- spline accumulate: block per node, SMEM tile, no atomics ----------------
#define CHK 64
__global__ void __launch_bounds__(64) spline_node_kernel(const float* __restrict__ x,
                                                         const int*   __restrict__ ei,
                                                         const float* __restrict__ ea) {
    __shared__ float sacc[PIN];            // 6.9 KB
    __shared__ int   s_src[CHK];
    __shared__ float s_v[CHK][3];
    __shared__ float s_xj[CHK][KIN];       // 16 KB
    int m = blockIdx.x, o = threadIdx.x;
    #pragma unroll
    for (int k = o; k < PIN; k += 64) sacc[k] = 0.f;
    int st = g_eoff[m], cnt = g_ecnt[m];

    for (int c0 = 0; c0 < cnt; c0 += CHK) {
        int ce = min(CHK, cnt - c0);
        __syncthreads();
        int k = c0 + o;
        if (k < cnt) {
            int e = __ldg(&g_elist[st + k]);
            s_src[o]   = __ldg(&ei[e]);
            s_v[o][0]  = __ldg(&ea[3 * e]);
            s_v[o][1]  = __ldg(&ea[3 * e + 1]);
            s_v[o][2]  = __ldg(&ea[3 * e + 2]);
        }
        __syncthreads();
        // stage all x_j rows in parallel (huge MLP, latency hidden)
        for (int idx = o; idx < ce * KIN; idx += 64) {
            int j = idx >> 6, f = idx & 63;
            s_xj[j][f] = __ldg(&x[(size_t)s_src[j] * KIN + f]);
        }
        __syncthreads();
        for (int j = 0; j < ce; ++j) {
            float v0 = __fmul_rn(s_v[j][0], 2.0f);
            float v1 = __fmul_rn(s_v[j][1], 2.0f);
            float v2 = __fmul_rn(s_v[j][2], 2.0f);
            float k0 = fminf(fmaxf(floorf(v0), 0.f), 1.f);
            float k1 = fminf(fmaxf(floorf(v1), 0.f), 1.f);
            float k2 = fminf(fmaxf(floorf(v2), 0.f), 1.f);
            float f0 = v0 - k0, f1 = v1 - k1, f2 = v2 - k2;
            int pb = (int)k0 * 9 + (int)k1 * 3 + (int)k2;
            float xj = s_xj[j][o];
            float* ab = sacc + pb * KIN + o;
            #pragma unroll
            for (int s = 0; s < 8; ++s) {
                int b0 = s & 1, b1 = (s >> 1) & 1, b2 = (s >> 2) & 1;
                float b = b0 ? f0 : (1.0f - f0);
                b = __fmul_rn(b, b1 ? f1 : (1.0f - f1));
                b = __fmul_rn(b, b2 ? f2 : (1.0f - f2));
                int off = (b0 * 9 + b1 * 3 + b2) * KIN;
                ab[off] += __fmul_rn(b, xj);           // thread-private address
            }
        }
    }
    __syncthreads();
    size_t baseo = (size_t)m * PIN;
    #pragma unroll
    for (int k = o; k < PIN; k += 64) g_acc[baseo + k] = sacc[k];
}

// ---------------- GEMM + root + bias + ELU (8 nodes per block) ----------------
__global__ void node_out_kernel(const float* __restrict__ x,
                                const float* __restrict__ W,
                                const float* __restrict__ rootw,
                                const float* __restrict__ bias,
                                float* __restrict__ out) {
    int m0 = blockIdx.x * 8;
    int o  = threadIdx.x;
    const float* a = g_acc + (size_t)m0 * PIN;
    float s[8] = {0.f, 0.f, 0.f, 0.f, 0.f, 0.f, 0.f, 0.f};
    #pragma unroll 4
    for (int k = 0; k < PIN; ++k) {
        float w = __ldg(&W[k * KIN + o]);
        #pragma unroll
        for (int j = 0; j < 8; ++j)
            s[j] += __ldg(&a[(size_t)j * PIN + k]) * w;
    }
    float b = bias[o];
    for (int j = 0; j < 8; ++j) {
        int m = m0 + j;
        float v = s[j] / fmaxf((float)g_ecnt[m], 1.0f);
        int node = g_idx[m];
        const float* xr = x + (size_t)node * KIN;
        #pragma unroll 8
        for (int i = 0; i < KIN; ++i)
            v += __ldg(&xr[i]) * __ldg(&rootw[i * KIN + o]);
        v += b;
        v = (v > 0.f) ? v : expm1f(v);
        out[SEC_X + m * KIN + o] = v;
    }
}

// ---------------- radius: grid candidates + 20000-bit bitmap, ordered emit ----------------
#define RW 625   // 20000/32
__global__ void __launch_bounds__(128) radius_kernel(float* __restrict__ out) {
    __shared__ unsigned s_bm[RW];
    __shared__ int s_cells[32];
    __shared__ int s_ncell;
    int m = blockIdx.x, tid = threadIdx.x;
    int node = g_idx[m];
    float4 q = g_pos4[node];                // q.w = qn (reference formula)
    for (int i = tid; i < RW; i += 128) s_bm[i] = 0u;
    if (tid == 0) {
        int lo[3], hi[3];
        float qc[3] = {q.x, q.y, q.z};
        for (int d = 0; d < 3; ++d) {
            lo[d] = max(0, (int)floorf((qc[d] - 0.1f) * 8.0f - 1e-3f));
            hi[d] = min(7, (int)floorf((qc[d] + 0.1f) * 8.0f + 1e-3f));
        }
        int n = 0;
        for (int cx = lo[0]; cx <= hi[0]; ++cx)
            for (int cy = lo[1]; cy <= hi[1]; ++cy)
                for (int cz = lo[2]; cz <= hi[2]; ++cz)
                    s_cells[n++] = (cx << 6) | (cy << 3) | cz;
        s_ncell = n;
    }
    __syncthreads();
    int nc = s_ncell;
    for (int ci = 0; ci < nc; ++ci) {
        int cid = s_cells[ci];
        int st = g_cellstart[cid], en = g_cellstart[cid + 1];
        for (int i = st + tid; i < en; i += 128) {
            float4 p = __ldg(&g_spos[i]);
            float an = __fadd_rn(__fadd_rn(__fmul_rn(p.x, p.x), __fmul_rn(p.y, p.y)),
                                 __fmul_rn(p.z, p.z));
            float dot = __fadd_rn(__fadd_rn(__fmul_rn(q.x, p.x), __fmul_rn(q.y, p.y)),
                                  __fmul_rn(q.z, p.z));
            float d2 = __fadd_rn(__fadd_rn(q.w, an), -__fmul_rn(2.0f, dot));
            if (d2 < R2c) {
                int oi = __float_as_int(p.w);
                atomicOr(&s_bm[oi >> 5], 1u << (oi & 31));
            }
        }
    }
    __syncthreads();
    if (tid < 32) {
        int lane = tid;
        int base = 0;
        for (int w0 = 0; w0 < RW; w0 += 32) {
            unsigned word = (w0 + lane < RW) ? s_bm[w0 + lane] : 0u;
            int pc = __popc(word);
            int ex = pc;
            #pragma unroll
            for (int o = 1; o < 32; o <<= 1) {
                int v = __shfl_up_sync(0xffffffffu, ex, o);
                if (lane >= o) ex += v;
            }
            int tot = __shfl_sync(0xffffffffu, ex, 31);
            ex -= pc;
            int pos = base + ex;
            while (word && pos < MAXNb) {
                int b = __ffs(word) - 1;
                word &= word - 1;
                int oi = (w0 + lane) * 32 + b;
                out[SEC_COL + m * MAXNb + pos] = (float)oi;
                out[SEC_ROW + m * MAXNb + pos] = (float)m;
                ++pos;
            }
            base += tot;
            if (base >= MAXNb) break;
        }
        for (int j = base + lane; j < MAXNb; j += 32) {
            out[SEC_COL + m * MAXNb + j] = -1.0f;
            out[SEC_ROW + m * MAXNb + j] = -1.0f;
        }
    }
}

// ---------------- tail gathers ----------------
__global__ void tail_kernel(const float* __restrict__ pos,
                            const float* __restrict__ ea,
                            float* __restrict__ out) {
    int m = blockIdx.x * blockDim.x + threadIdx.x;
    if (m >= Mm) return;
    int node = g_idx[m];
    out[SEC_POS + 3 * m + 0] = pos[3 * node + 0];
    out[SEC_POS + 3 * m + 1] = pos[3 * node + 1];
    out[SEC_POS + 3 * m + 2] = pos[3 * node + 2];
    out[SEC_BATCH + m]       = 0.0f;
    out[SEC_EA + 3 * m + 0]  = ea[3 * node + 0];
    out[SEC_EA + 3 * m + 1]  = ea[3 * node + 1];
    out[SEC_EA + 3 * m + 2]  = ea[3 * node + 2];
}

// ---------------- launch ----------------
extern "C" void kernel_launch(void* const* d_in, const int* in_sizes, int n_in,
                              void* d_out, int out_size) {
    const float* x     = (const float*)d_in[0];
    const int*   ei    = (const int*)d_in[1];
    const float* ea    = (const float*)d_in[2];
    const float* pos   = (const float*)d_in[3];
    const float* W     = (const float*)d_in[5];
    const float* rootw = (const float*)d_in[6];
    const float* bias  = (const float*)d_in[7];
    float* out = (float*)d_out;

    cudaFuncSetAttribute(fps_kernel, cudaFuncAttributeMaxDynamicSharedMemorySize,
                         FPS_SMEM);

    prep_kernel<<<(Nn + 255) / 256, 256>>>(pos);
    zero_cnt_kernel<<<1, NC>>>();
    cell_hist_kernel<<<(Nn + 255) / 256, 256>>>(pos);
    cell_scan_kernel<<<1, NC>>>();
    cell_scatter_kernel<<<(Nn + 255) / 256, 256>>>(pos);

    fps_kernel<<<1, 256, FPS_SMEM>>>();

    sel_init_kernel<<<(Nn + 255) / 256, 256>>>();
    sel_set_kernel<<<(Mm + 255) / 256, 256>>>();
    edge_hist_kernel<<<(Ee + 255) / 256, 256>>>(ei);
    edge_scan_kernel<<<1, 1024>>>();
    edge_fill_kernel<<<(Ee + 255) / 256, 256>>>(ei);

    spline_node_kernel<<<Mm, 64>>>(x, ei, ea);
    node_out_kernel<<<Mm / 8, KIN>>>(x, W, rootw, bias, out);
    radius_kernel<<<Mm, 128>>>(out);
    tail_kernel<<<(Mm + 127) / 128, 128>>>(pos, ea, out);
}